// round 8
// baseline (speedup 1.0000x reference)
#include <cuda_runtime.h>
#include <cuda_bf16.h>

// WaveletTransformLayer: x (B=128, T=2048, F=32) f32.
// Per (b,f): d1 (2047) | d2 (2044) | d3 (2037) | ma3 (2037), each / T.
//   m2[t] = 8*ma2[t] = x[t] + 2(x[t+1]+x[t+2]+x[t+3]) + x[t+4]
//   S[t]  = 64*ma3[t] = sum_{j=0..7} m2[t+j]
//   d1[t] = (x[t+1]-x[t])/2 ; d2[t] = (x[t+3]+x[t+4])/2 - m2[t]/8
//   d3[t] = m2[t+7]/8 - S[t]/64 ; ma3[t] = S[t]/64     (all x 1/T)
//
// R8: lane=f sliding-window compute. Input read directly from global
// (coalesced LDG.32, no input smem, ~2.4x read amplification vs 12x smem
// re-reads in R5). Outputs transposed via a 16.9KB staging buffer to keep
// stores coalesced. Warp = 8-t strip; block = 32-t chunk x 32 f; warp w
// stores segment w. Grid 1024 x 8 units each: balanced single wave.

#define T_LEN     2048
#define F_DIM     32
#define OUT_PER_F 8165
#define SEG1      2047
#define SEG2      4091
#define SEG3      6128
#define CHUNK     32
#define NCHUNK    64            // 2048 / 32
#define NUNITS    8192          // 128 b * 64 chunks
#define GRID      1024          // 8 units per block, balanced
#define SP        33            // staging pitch (floats)
#define SSEG      (CHUNK * SP)  // 1056 floats per segment buffer

__global__ __launch_bounds__(128, 8)
void wavelet_kernel(const float* __restrict__ x, float* __restrict__ out) {
    __shared__ float st[4 * SSEG];   // 4 * 1056 * 4B = 16896 B

    const int tid = threadIdx.x;
    const int w   = tid >> 5;        // warp 0..3 -> t-strip / store segment
    const int l   = tid & 31;        // lane: feature (compute), t (store)

    const int segoff = (w == 0) ? 0 : (w == 1) ? SEG1 : (w == 2) ? SEG2 : SEG3;
    const int lim    = (w == 0) ? 2047 : (w == 1) ? 2044 : 2037;

    const float inv   = 1.0f / 2048.0f;
    const float inv2  = inv * 0.5f;
    const float inv8  = inv * 0.125f;
    const float inv64 = inv * 0.015625f;

    const int  c    = blockIdx.x & (NCHUNK - 1);  // constant across iterations
    const int  T0   = c * CHUNK;
    const int  tb   = T0 + 8 * w;                 // this warp's t-strip base
    const bool last = (c == NCHUNK - 1);

    for (int u = blockIdx.x; u < NUNITS; u += GRID) {
        const int b = u >> 6;
        const float* base = x + (size_t)b * (T_LEN * F_DIM);

        // ---- Load 19-value window per lane (coalesced: 32 lanes = 32 consecutive f) ----
        float xv[19];
        if (!last) {
            const float* p = base + tb * F_DIM + l;
            #pragma unroll
            for (int j = 0; j < 19; ++j) xv[j] = p[F_DIM * j];
        } else {
            #pragma unroll
            for (int j = 0; j < 19; ++j) {
                int tt = tb + j; if (tt > T_LEN - 1) tt = T_LEN - 1;  // clamp; excess unused
                xv[j] = base[tt * F_DIM + l];
            }
        }

        // ---- FIR pyramid in registers ----
        float m2[15];
        #pragma unroll
        for (int i = 0; i < 15; ++i)
            m2[i] = (xv[i] + xv[i + 4]) + 2.0f * ((xv[i + 1] + xv[i + 2]) + xv[i + 3]);

        float S = ((m2[0] + m2[1]) + (m2[2] + m2[3]))
                + ((m2[4] + m2[5]) + (m2[6] + m2[7]));

        float* srow = st + (8 * w) * SP + l;   // stage[seg][tl][f=l]
        #pragma unroll
        for (int k = 0; k < 8; ++k) {
            float d1 = (xv[k + 1] - xv[k]) * inv2;
            float d2 = (xv[k + 3] + xv[k + 4]) * inv2 - m2[k] * inv8;
            float d3 = m2[k + 7] * inv8 - S * inv64;
            float m3 = S * inv64;
            srow[k * SP]            = d1;      // conflict-free: consecutive lanes/banks
            srow[k * SP + SSEG]     = d2;
            srow[k * SP + 2 * SSEG] = d3;
            srow[k * SP + 3 * SSEG] = m3;
            if (k < 7) S += m2[k + 8] - m2[k];
        }
        __syncthreads();

        // ---- Store: warp w -> segment w, lane = t, loop f (coalesced STG.32) ----
        const float* sp = st + w * SSEG + l * SP;   // stride-33 read: conflict-free
        float* op = out + (size_t)b * (F_DIM * OUT_PER_F) + segoff + T0 + l;
        if (!last) {
            #pragma unroll 8
            for (int f = 0; f < F_DIM; ++f) op[(size_t)f * OUT_PER_F] = sp[f];
        } else {
            if (T0 + l < lim) {
                #pragma unroll 8
                for (int f = 0; f < F_DIM; ++f) op[(size_t)f * OUT_PER_F] = sp[f];
            }
        }
        __syncthreads();   // protect staging reuse across units
    }
}

extern "C" void kernel_launch(void* const* d_in, const int* in_sizes, int n_in,
                              void* d_out, int out_size) {
    const float* x = (const float*)d_in[0];
    float* out = (float*)d_out;
    wavelet_kernel<<<GRID, 128>>>(x, out);
}

// round 9
// speedup vs baseline: 1.0370x; 1.0370x over previous
#include <cuda_runtime.h>
#include <cuda_bf16.h>

// WaveletTransformLayer: x (B=128, T=2048, F=32) f32.
// Per (b,f): d1 (2047) | d2 (2044) | d3 (2037) | ma3 (2037), each / T.
//   m2[t] = 8*ma2[t] = x[t] + 2(x[t+1]+x[t+2]+x[t+3]) + x[t+4]
//   S[t]  = 64*ma3[t] = sum_{j=0..7} m2[t+j]
//   d1[t] = (x[t+1]-x[t])/2 ; d2[t] = (x[t+3]+x[t+4])/2 - m2[t]/8
//   d3[t] = m2[t+7]/8 - S[t]/64 ; ma3[t] = S[t]/64     (all x 1/T)
//
// R8: lane=f sliding-window compute. Input read directly from global
// (coalesced LDG.32, no input smem, ~2.4x read amplification vs 12x smem
// re-reads in R5). Outputs transposed via a 16.9KB staging buffer to keep
// stores coalesced. Warp = 8-t strip; block = 32-t chunk x 32 f; warp w
// stores segment w. Grid 1024 x 8 units each: balanced single wave.

#define T_LEN     2048
#define F_DIM     32
#define OUT_PER_F 8165
#define SEG1      2047
#define SEG2      4091
#define SEG3      6128
#define CHUNK     32
#define NCHUNK    64            // 2048 / 32
#define NUNITS    8192          // 128 b * 64 chunks
#define GRID      1024          // 8 units per block, balanced
#define SP        33            // staging pitch (floats)
#define SSEG      (CHUNK * SP)  // 1056 floats per segment buffer

__global__ __launch_bounds__(128, 8)
void wavelet_kernel(const float* __restrict__ x, float* __restrict__ out) {
    __shared__ float st[4 * SSEG];   // 4 * 1056 * 4B = 16896 B

    const int tid = threadIdx.x;
    const int w   = tid >> 5;        // warp 0..3 -> t-strip / store segment
    const int l   = tid & 31;        // lane: feature (compute), t (store)

    const int segoff = (w == 0) ? 0 : (w == 1) ? SEG1 : (w == 2) ? SEG2 : SEG3;
    const int lim    = (w == 0) ? 2047 : (w == 1) ? 2044 : 2037;

    const float inv   = 1.0f / 2048.0f;
    const float inv2  = inv * 0.5f;
    const float inv8  = inv * 0.125f;
    const float inv64 = inv * 0.015625f;

    const int  c    = blockIdx.x & (NCHUNK - 1);  // constant across iterations
    const int  T0   = c * CHUNK;
    const int  tb   = T0 + 8 * w;                 // this warp's t-strip base
    const bool last = (c == NCHUNK - 1);

    for (int u = blockIdx.x; u < NUNITS; u += GRID) {
        const int b = u >> 6;
        const float* base = x + (size_t)b * (T_LEN * F_DIM);

        // ---- Load 19-value window per lane (coalesced: 32 lanes = 32 consecutive f) ----
        float xv[19];
        if (!last) {
            const float* p = base + tb * F_DIM + l;
            #pragma unroll
            for (int j = 0; j < 19; ++j) xv[j] = p[F_DIM * j];
        } else {
            #pragma unroll
            for (int j = 0; j < 19; ++j) {
                int tt = tb + j; if (tt > T_LEN - 1) tt = T_LEN - 1;  // clamp; excess unused
                xv[j] = base[tt * F_DIM + l];
            }
        }

        // ---- FIR pyramid in registers ----
        float m2[15];
        #pragma unroll
        for (int i = 0; i < 15; ++i)
            m2[i] = (xv[i] + xv[i + 4]) + 2.0f * ((xv[i + 1] + xv[i + 2]) + xv[i + 3]);

        float S = ((m2[0] + m2[1]) + (m2[2] + m2[3]))
                + ((m2[4] + m2[5]) + (m2[6] + m2[7]));

        float* srow = st + (8 * w) * SP + l;   // stage[seg][tl][f=l]
        #pragma unroll
        for (int k = 0; k < 8; ++k) {
            float d1 = (xv[k + 1] - xv[k]) * inv2;
            float d2 = (xv[k + 3] + xv[k + 4]) * inv2 - m2[k] * inv8;
            float d3 = m2[k + 7] * inv8 - S * inv64;
            float m3 = S * inv64;
            srow[k * SP]            = d1;      // conflict-free: consecutive lanes/banks
            srow[k * SP + SSEG]     = d2;
            srow[k * SP + 2 * SSEG] = d3;
            srow[k * SP + 3 * SSEG] = m3;
            if (k < 7) S += m2[k + 8] - m2[k];
        }
        __syncthreads();

        // ---- Store: warp w -> segment w, lane = t, loop f (coalesced STG.32) ----
        const float* sp = st + w * SSEG + l * SP;   // stride-33 read: conflict-free
        float* op = out + (size_t)b * (F_DIM * OUT_PER_F) + segoff + T0 + l;
        if (!last) {
            #pragma unroll 8
            for (int f = 0; f < F_DIM; ++f) op[(size_t)f * OUT_PER_F] = sp[f];
        } else {
            if (T0 + l < lim) {
                #pragma unroll 8
                for (int f = 0; f < F_DIM; ++f) op[(size_t)f * OUT_PER_F] = sp[f];
            }
        }
        __syncthreads();   // protect staging reuse across units
    }
}

extern "C" void kernel_launch(void* const* d_in, const int* in_sizes, int n_in,
                              void* d_out, int out_size) {
    const float* x = (const float*)d_in[0];
    float* out = (float*)d_out;
    wavelet_kernel<<<GRID, 128>>>(x, out);
}